// round 9
// baseline (speedup 1.0000x reference)
#include <cuda_runtime.h>
#include <math.h>
#include <stdint.h>

// Problem constants
#define BSZ 64
#define SEQ 512
#define DIM 768
#define NSPANS 1280
#define LMAX 5
#define H 200
#define G4 800          // 4*H
#define NENT 16
#define MROWS (NSPANS*LMAX)   // 6400

// Scratch (device globals)
__device__ float d_xg    [2ll * MROWS * G4];
__device__ float d_sum   [2ll * NSPANS * H];
__device__ int   d_offset[NSPANS + 1];
__device__ int   d_rowmap[MROWS];

// ---------------------------------------------------------------------------
// tf32 helpers
// ---------------------------------------------------------------------------
__device__ __forceinline__ uint32_t f2tf32(float f) {
    uint32_t r;
    asm("cvt.rna.tf32.f32 %0, %1;" : "=r"(r) : "f"(f));
    return r;
}

__device__ __forceinline__ void mma_tf32(float* c, const uint32_t* a, const uint32_t* b) {
    asm volatile(
        "mma.sync.aligned.m16n8k8.row.col.f32.tf32.tf32.f32 "
        "{%0,%1,%2,%3}, {%4,%5,%6,%7}, {%8,%9}, {%0,%1,%2,%3};"
        : "+f"(c[0]), "+f"(c[1]), "+f"(c[2]), "+f"(c[3])
        : "r"(a[0]), "r"(a[1]), "r"(a[2]), "r"(a[3]), "r"(b[0]), "r"(b[1]));
}

__device__ __forceinline__ float sigm(float x) { return 1.f / (1.f + expf(-x)); }

#define BK 32
#define PAD 4
#define LDSROW (BK + PAD)   // 36 uints per row (R4 proven layout)

// ---------------------------------------------------------------------------
// Compaction: offsets = exclusive-prefix(slen); rowmap[off+l] = (n<<3)|l
// ---------------------------------------------------------------------------
__global__ void compact_kernel(const int* __restrict__ slen)
{
    __shared__ int part[256];
    int tid = threadIdx.x;
    int base = tid * 5;
    int loc[5], s = 0;
#pragma unroll
    for (int i = 0; i < 5; i++) { loc[i] = s; s += slen[base + i]; }
    part[tid] = s;
    __syncthreads();
    for (int off = 1; off < 256; off <<= 1) {
        int v = (tid >= off) ? part[tid - off] : 0;
        __syncthreads();
        part[tid] += v;
        __syncthreads();
    }
    int pre = (tid == 0) ? 0 : part[tid - 1];
#pragma unroll
    for (int i = 0; i < 5; i++) {
        int n = base + i;
        int off = pre + loc[i];
        d_offset[n] = off;
        int ln = slen[n];
        for (int l = 0; l < ln; l++)
            d_rowmap[off + l] = (n << 3) | l;
    }
    if (tid == 255) d_offset[NSPANS] = part[255];
}

// ---------------------------------------------------------------------------
// xg GEMM, fused gather, compacted rows (unchanged from R8)
// ---------------------------------------------------------------------------
__global__ __launch_bounds__(256)
void gemm_xg_kernel(const float* __restrict__ hidden,
                    const int* __restrict__ tok,
                    const int* __restrict__ slen,
                    const int* __restrict__ sbatch,
                    const float* __restrict__ Wf, const float* __restrict__ bif,
                    const float* __restrict__ bhf,
                    const float* __restrict__ Wb, const float* __restrict__ bib,
                    const float* __restrict__ bhb)
{
    const int BM = 128, BN = 64, K = DIM, N = G4;
    int m0 = blockIdx.y * BM;
    int count = d_offset[NSPANS];
    if (m0 >= count) return;

    __shared__ uint32_t As[BM][LDSROW];
    __shared__ uint32_t Bs[BN][LDSROW];
    __shared__ const float* rowptr[BM];

    int dir = blockIdx.z;
    const float* W  = dir ? Wb : Wf;
    const float* c1 = dir ? bib : bif;
    const float* c2 = dir ? bhb : bhf;
    float* C        = d_xg + (size_t)dir * MROWS * G4;

    int tid  = threadIdx.x;
    int warp = tid >> 5, lane = tid & 31;
    int wm = warp & 3, wn = warp >> 2;
    int grp = lane >> 2, qid = lane & 3;
    int n0 = blockIdx.x * BN;

    if (tid < BM) {
        int r = m0 + tid;
        const float* p = nullptr;
        if (r < count) {
            int rm = d_rowmap[r];
            int n  = rm >> 3;
            int l  = rm & 7;
            int ln = slen[n];
            int sl = dir ? (ln - 1 - l) : l;
            int t  = tok[n * LMAX + sl];
            int b  = sbatch[n];
            p = hidden + ((size_t)b * SEQ + t) * DIM;
        }
        rowptr[tid] = p;
    }
    __syncthreads();

    float acc[2][4][4];
#pragma unroll
    for (int i = 0; i < 2; i++)
#pragma unroll
        for (int j = 0; j < 4; j++)
#pragma unroll
            for (int q = 0; q < 4; q++) acc[i][j][q] = 0.f;

    const int lrow = tid >> 3;
    const int lcol = (tid & 7) * 4;

    for (int kt = 0; kt < K; kt += BK) {
#pragma unroll
        for (int p = 0; p < BM / 32; p++) {
            int m = lrow + p * 32;
            const float* src = rowptr[m];
            float4 v = make_float4(0.f, 0.f, 0.f, 0.f);
            if (src)
                v = *(const float4*)(src + kt + lcol);
            uint4 t;
            t.x = f2tf32(v.x); t.y = f2tf32(v.y);
            t.z = f2tf32(v.z); t.w = f2tf32(v.w);
            *(uint4*)&As[m][lcol] = t;
        }
#pragma unroll
        for (int p = 0; p < BN / 32; p++) {
            int n = lrow + p * 32;
            float4 v = make_float4(0.f, 0.f, 0.f, 0.f);
            if (n0 + n < N)
                v = *(const float4*)(W + (size_t)(n0 + n) * DIM + kt + lcol);
            uint4 t;
            t.x = f2tf32(v.x); t.y = f2tf32(v.y);
            t.z = f2tf32(v.z); t.w = f2tf32(v.w);
            *(uint4*)&Bs[n][lcol] = t;
        }
        __syncthreads();

#pragma unroll
        for (int ks = 0; ks < BK / 8; ks++) {
            uint32_t af[2][4], bf[4][2];
#pragma unroll
            for (int i = 0; i < 2; i++) {
                int mr = wm * 32 + i * 16;
                af[i][0] = As[mr + grp    ][ks * 8 + qid    ];
                af[i][1] = As[mr + grp + 8][ks * 8 + qid    ];
                af[i][2] = As[mr + grp    ][ks * 8 + qid + 4];
                af[i][3] = As[mr + grp + 8][ks * 8 + qid + 4];
            }
#pragma unroll
            for (int j = 0; j < 4; j++) {
                int nr = wn * 32 + j * 8;
                bf[j][0] = Bs[nr + grp][ks * 8 + qid    ];
                bf[j][1] = Bs[nr + grp][ks * 8 + qid + 4];
            }
#pragma unroll
            for (int i = 0; i < 2; i++)
#pragma unroll
                for (int j = 0; j < 4; j++)
                    mma_tf32(acc[i][j], af[i], bf[j]);
        }
        __syncthreads();
    }

#pragma unroll
    for (int i = 0; i < 2; i++) {
#pragma unroll
        for (int j = 0; j < 4; j++) {
            int m = m0 + wm * 32 + i * 16 + grp;
            int n = n0 + wn * 32 + j * 8 + qid * 2;
            if (n < N) {
                float bb0 = c1[n] + c2[n];
                float bb1 = c1[n + 1] + c2[n + 1];
                C[(size_t)m * G4 + n]           = acc[i][j][0] + bb0;
                C[(size_t)m * G4 + n + 1]       = acc[i][j][1] + bb1;
                C[(size_t)(m + 8) * G4 + n]     = acc[i][j][2] + bb0;
                C[(size_t)(m + 8) * G4 + n + 1] = acc[i][j][3] + bb1;
            }
        }
    }
}

// ---------------------------------------------------------------------------
// Span-resident persistent recurrence: one launch, all 5 time steps.
// Block = 32 spans x 1 dir. h (tf32 frags), c, sum live in smem.
// Per step: 13 chunks of 64 gate-cols (4 gates x 16 hh); W streamed from L2.
// grid = (40, 2), 256 threads, dynamic smem 176896 B.
// ---------------------------------------------------------------------------
#define RS 32
#define KP 228     // uint stride; 228 % 32 == 4 -> conflict-free frag LDS

#define SM_AH    0
#define SM_BS    58368
#define SM_GS    116736
#define SM_C     125440
#define SM_SUM   151040
#define SM_LENS  176640
#define SM_OFFS  176768
#define SM_TOTAL 176896

__global__ __launch_bounds__(256)
void recurrence_kernel(const float* __restrict__ Wf, const float* __restrict__ Wb,
                       const int* __restrict__ slen)
{
    extern __shared__ unsigned char smem[];
    uint32_t* Ah    = (uint32_t*)(smem + SM_AH);    // [2][RS][KP]
    uint32_t* Bs    = (uint32_t*)(smem + SM_BS);    // [64][KP]
    float*    Gs    = (float*)   (smem + SM_GS);    // [RS][68]
    float*    c_s   = (float*)   (smem + SM_C);     // [RS][H]
    float*    sum_s = (float*)   (smem + SM_SUM);   // [RS][H]
    int*      lens  = (int*)     (smem + SM_LENS);
    int*      offs  = (int*)     (smem + SM_OFFS);

    int dir = blockIdx.y;
    int m0  = blockIdx.x * RS;
    const float* W  = dir ? Wb : Wf;
    const float* XG = d_xg + (size_t)dir * MROWS * G4;

    int tid  = threadIdx.x;
    int warp = tid >> 5, lane = tid & 31;
    int wm = warp & 1, wn = warp >> 1;
    int grp = lane >> 2, qid = lane & 3;

    if (tid < RS) {
        int n = m0 + tid;
        lens[tid] = slen[n];
        offs[tid] = d_offset[n];
    }
    // zero both h buffers (incl. k-padding cols)
    for (int i = tid; i < 2 * RS * KP; i += 256) Ah[i] = 0;
    __syncthreads();

    // t = 0 cell: gates = xg[offset[n]] (h=0)
    for (int id = tid; id < RS * H; id += 256) {
        int m = id / H, hh = id - m * H;
        const float* g = XG + (size_t)offs[m] * G4 + hh;
        float gi = g[0], gg = g[2 * H], go = g[3 * H];
        float cn = sigm(gi) * tanhf(gg);
        float hn = sigm(go) * tanhf(cn);
        c_s[id]   = cn;
        sum_s[id] = hn;                 // slen >= 1
        Ah[m * KP + hh] = f2tf32(hn);   // parity 0
    }
    __syncthreads();

    int cur = 0;
    for (int t = 1; t < LMAX; t++) {
        int nxt = cur ^ 1;
        for (int ch = 0; ch < 13; ch++) {
            int hh_base = ch * 16;
            // Load B chunk: 64 gate-columns x full K, row -> (n>>4)*H + hh
            for (int idx = tid; idx < 64 * 52; idx += 256) {
                int row = idx / 52, c4 = idx - row * 52;
                int k = c4 * 4;
                int hhi = hh_base + (row & 15);
                float4 v = make_float4(0.f, 0.f, 0.f, 0.f);
                if (hhi < H && k < 197)
                    v = *(const float4*)(W + (size_t)((row >> 4) * H + hhi) * H + k);
                uint32_t* dst = Bs + row * KP + k;
                dst[0] = f2tf32(v.x); dst[1] = f2tf32(v.y);
                dst[2] = f2tf32(v.z); dst[3] = f2tf32(v.w);
            }
            __syncthreads();

            // GEMM: 25 k8 steps against resident h
            float acc[2][4];
#pragma unroll
            for (int j = 0; j < 2; j++)
#pragma unroll
                for (int q = 0; q < 4; q++) acc[j][q] = 0.f;

            const uint32_t* Ac = Ah + cur * RS * KP;
#pragma unroll 5
            for (int k8 = 0; k8 < 25; k8++) {
                int col = k8 * 8 + qid;
                uint32_t af[4];
                af[0] = Ac[(wm * 16 + grp    ) * KP + col];
                af[1] = Ac[(wm * 16 + grp + 8) * KP + col];
                af[2] = Ac[(wm * 16 + grp    ) * KP + col + 4];
                af[3] = Ac[(wm * 16 + grp + 8) * KP + col + 4];
#pragma unroll
                for (int j = 0; j < 2; j++) {
                    int nr = wn * 16 + j * 8;
                    uint32_t bf[2];
                    bf[0] = Bs[(nr + grp) * KP + col];
                    bf[1] = Bs[(nr + grp) * KP + col + 4];
                    mma_tf32(acc[j], af, bf);
                }
            }

            // Stage gates
#pragma unroll
            for (int j = 0; j < 2; j++) {
                int n = wn * 16 + j * 8 + qid * 2;
                int m = wm * 16 + grp;
                Gs[m * 68 + n]           = acc[j][0];
                Gs[m * 68 + n + 1]       = acc[j][1];
                Gs[(m + 8) * 68 + n]     = acc[j][2];
                Gs[(m + 8) * 68 + n + 1] = acc[j][3];
            }
            __syncthreads();

            // Cell: 32 x 16 items, 2 per thread
#pragma unroll
            for (int it = 0; it < 2; it++) {
                int id = tid + it * 256;
                int m = id >> 4, hl = id & 15;
                int hh = hh_base + hl;
                if (hh < H) {
                    int len = lens[m];
                    int tt = t < len ? t : len - 1;
                    size_t xb = (size_t)(offs[m] + tt) * G4 + hh;
                    float gi = Gs[m * 68 + hl     ] + XG[xb];
                    float gf = Gs[m * 68 + 16 + hl] + XG[xb + H];
                    float gg = Gs[m * 68 + 32 + hl] + XG[xb + 2 * H];
                    float go = Gs[m * 68 + 48 + hl] + XG[xb + 3 * H];
                    float cp = c_s[m * H + hh];
                    float cn = sigm(gf) * cp + sigm(gi) * tanhf(gg);
                    float hn = sigm(go) * tanhf(cn);
                    c_s[m * H + hh] = cn;
                    if (t < len) sum_s[m * H + hh] += hn;
                    Ah[nxt * RS * KP + m * KP + hh] = f2tf32(hn);
                }
            }
            // next chunk's post-Bs-load sync orders Gs/Bs reuse
        }
        cur = nxt;
    }

    __syncthreads();
    // Write masked sums out for logits
    for (int id = tid; id < RS * H; id += 256)
        d_sum[(size_t)dir * NSPANS * H + (size_t)m0 * H + id] = sum_s[id];
}

// ---------------------------------------------------------------------------
// Logits
// ---------------------------------------------------------------------------
__global__ void logits_kernel(const float* __restrict__ E,
                              float* __restrict__ out)
{
    int idx = blockIdx.x * blockDim.x + threadIdx.x;
    if (idx >= NSPANS * NENT) return;
    int e = idx % NENT;
    int n = idx / NENT;

    const float4* sf = (const float4*)(d_sum + (size_t)n * H);
    const float4* sb = (const float4*)(d_sum + (size_t)NSPANS * H + (size_t)n * H);
    const float4* er = (const float4*)(E + (size_t)e * 2 * H);

    float acc = 0.f;
#pragma unroll
    for (int j = 0; j < H / 4; j++) {
        float4 a = sf[j], b = er[j];
        acc += a.x * b.x + a.y * b.y + a.z * b.z + a.w * b.w;
    }
#pragma unroll
    for (int j = 0; j < H / 4; j++) {
        float4 a = sb[j], b = er[H / 4 + j];
        acc += a.x * b.x + a.y * b.y + a.z * b.z + a.w * b.w;
    }
    out[idx] = acc;
}

// ---------------------------------------------------------------------------
// Launch
// ---------------------------------------------------------------------------
extern "C" void kernel_launch(void* const* d_in, const int* in_sizes, int n_in,
                              void* d_out, int out_size)
{
    const float* hidden = (const float*)d_in[0];
    const int*   tok    = (const int*)d_in[1];
    const int*   slen   = (const int*)d_in[2];
    const int*   sbatch = (const int*)d_in[3];
    const float* W_ih_f = (const float*)d_in[4];
    const float* W_hh_f = (const float*)d_in[5];
    const float* b_ih_f = (const float*)d_in[6];
    const float* b_hh_f = (const float*)d_in[7];
    const float* W_ih_b = (const float*)d_in[8];
    const float* W_hh_b = (const float*)d_in[9];
    const float* b_ih_b = (const float*)d_in[10];
    const float* b_hh_b = (const float*)d_in[11];
    const float* E      = (const float*)d_in[12];
    float* out          = (float*)d_out;

    cudaFuncSetAttribute(recurrence_kernel,
                         cudaFuncAttributeMaxDynamicSharedMemorySize, SM_TOTAL);

    // 0. Row compaction
    compact_kernel<<<1, 256>>>(slen);

    // 1. xg GEMM, fused gather, compacted rows
    {
        dim3 grid((G4 + 63) / 64, MROWS / 128, 2);
        gemm_xg_kernel<<<grid, 256>>>(hidden, tok, slen, sbatch,
                                      W_ih_f, b_ih_f, b_hh_f,
                                      W_ih_b, b_ih_b, b_hh_b);
    }

    // 2. Persistent recurrence: single launch for all time steps
    {
        dim3 grid(NSPANS / RS, 2);
        recurrence_kernel<<<grid, 256, SM_TOTAL>>>(W_hh_f, W_hh_b, slen);
    }

    // 3. Logits
    logits_kernel<<<(NSPANS * NENT + 127) / 128, 128>>>(E, out);
}

// round 10
// speedup vs baseline: 1.7562x; 1.7562x over previous
#include <cuda_runtime.h>
#include <math.h>
#include <stdint.h>

// Problem constants
#define BSZ 64
#define SEQ 512
#define DIM 768
#define NSPANS 1280
#define LMAX 5
#define H 200
#define G4 800          // 4*H
#define NENT 16
#define MROWS (NSPANS*LMAX)   // 6400

// Scratch (device globals)
__device__ float d_xg    [2ll * MROWS * G4];
__device__ float d_h     [2ll * 2 * NSPANS * H];   // [parity][dir][pos][hh]
__device__ float d_c     [2ll * NSPANS * H];       // [dir][pos][hh]
__device__ float d_sum   [2ll * NSPANS * H];       // [dir][orig n][hh]
__device__ int   d_offset[NSPANS + 1];
__device__ int   d_rowmap[MROWS];
__device__ int   d_sorted[NSPANS];                 // pos -> orig span (len desc)
__device__ int   d_act   [LMAX];                   // act[t] = #spans with len > t

#define HBUF (2ll * NSPANS * H)

// ---------------------------------------------------------------------------
// tf32 helpers
// ---------------------------------------------------------------------------
__device__ __forceinline__ uint32_t f2tf32(float f) {
    uint32_t r;
    asm("cvt.rna.tf32.f32 %0, %1;" : "=r"(r) : "f"(f));
    return r;
}

__device__ __forceinline__ void mma_tf32(float* c, const uint32_t* a, const uint32_t* b) {
    asm volatile(
        "mma.sync.aligned.m16n8k8.row.col.f32.tf32.tf32.f32 "
        "{%0,%1,%2,%3}, {%4,%5,%6,%7}, {%8,%9}, {%0,%1,%2,%3};"
        : "+f"(c[0]), "+f"(c[1]), "+f"(c[2]), "+f"(c[3])
        : "r"(a[0]), "r"(a[1]), "r"(a[2]), "r"(a[3]), "r"(b[0]), "r"(b[1]));
}

__device__ __forceinline__ float sigm(float x) { return 1.f / (1.f + expf(-x)); }

#define BK 32
#define PAD 4
#define LDSROW (BK + PAD)   // 36 uints per row (proven layout)

// ---------------------------------------------------------------------------
// Compaction + length sort.
// offsets = exclusive-prefix(slen); rowmap; counting sort by len descending.
// ---------------------------------------------------------------------------
__global__ void compact_kernel(const int* __restrict__ slen)
{
    __shared__ int part[256];
    __shared__ int bins[8];
    __shared__ int starts[8];
    int tid = threadIdx.x;
    if (tid < 8) bins[tid] = 0;
    __syncthreads();

    int base = tid * 5;
    int loc[5], mylen[5], s = 0;
#pragma unroll
    for (int i = 0; i < 5; i++) {
        mylen[i] = slen[base + i];
        loc[i] = s; s += mylen[i];
        atomicAdd(&bins[mylen[i]], 1);
    }
    part[tid] = s;
    __syncthreads();
    for (int off = 1; off < 256; off <<= 1) {
        int v = (tid >= off) ? part[tid - off] : 0;
        __syncthreads();
        part[tid] += v;
        __syncthreads();
    }
    if (tid == 0) {
        int acc = 0;
        for (int l = 5; l >= 1; l--) { starts[l] = acc; acc += bins[l]; }
        d_act[0] = NSPANS;
        for (int t = 1; t < LMAX; t++) d_act[t] = starts[t];
    }
    __syncthreads();

    int pre = (tid == 0) ? 0 : part[tid - 1];
#pragma unroll
    for (int i = 0; i < 5; i++) {
        int n = base + i;
        int off = pre + loc[i];
        d_offset[n] = off;
        int ln = mylen[i];
        for (int l = 0; l < ln; l++)
            d_rowmap[off + l] = (n << 3) | l;
        int pos = atomicAdd(&starts[ln], 1);
        d_sorted[pos] = n;
    }
    if (tid == 255) d_offset[NSPANS] = part[255];
}

// ---------------------------------------------------------------------------
// xg GEMM, fused gather, compacted rows. BM=128, BN=128 (halves A re-reads).
// 8 warps (2Mx4N), warp tile 64x32 (MT=4, NT=4).
// ---------------------------------------------------------------------------
__global__ __launch_bounds__(256)
void gemm_xg_kernel(const float* __restrict__ hidden,
                    const int* __restrict__ tok,
                    const int* __restrict__ slen,
                    const int* __restrict__ sbatch,
                    const float* __restrict__ Wf, const float* __restrict__ bif,
                    const float* __restrict__ bhf,
                    const float* __restrict__ Wb, const float* __restrict__ bib,
                    const float* __restrict__ bhb)
{
    const int BM = 128, BN = 128, K = DIM, N = G4;
    int m0 = blockIdx.y * BM;
    int count = d_offset[NSPANS];
    if (m0 >= count) return;

    __shared__ uint32_t As[BM][LDSROW];
    __shared__ uint32_t Bs[BN][LDSROW];
    __shared__ const float* rowptr[BM];

    int dir = blockIdx.z;
    const float* W  = dir ? Wb : Wf;
    const float* c1 = dir ? bib : bif;
    const float* c2 = dir ? bhb : bhf;
    float* C        = d_xg + (size_t)dir * MROWS * G4;

    int tid  = threadIdx.x;
    int warp = tid >> 5, lane = tid & 31;
    int wm = warp & 1, wn = warp >> 1;
    int grp = lane >> 2, qid = lane & 3;
    int n0 = blockIdx.x * BN;

    if (tid < BM) {
        int r = m0 + tid;
        const float* p = nullptr;
        if (r < count) {
            int rm = d_rowmap[r];
            int n  = rm >> 3;
            int l  = rm & 7;
            int ln = slen[n];
            int sl = dir ? (ln - 1 - l) : l;
            int t  = tok[n * LMAX + sl];
            int b  = sbatch[n];
            p = hidden + ((size_t)b * SEQ + t) * DIM;
        }
        rowptr[tid] = p;
    }
    __syncthreads();

    float acc[4][4][4];
#pragma unroll
    for (int i = 0; i < 4; i++)
#pragma unroll
        for (int j = 0; j < 4; j++)
#pragma unroll
            for (int q = 0; q < 4; q++) acc[i][j][q] = 0.f;

    const int lrow = tid >> 3;
    const int lcol = (tid & 7) * 4;

    for (int kt = 0; kt < K; kt += BK) {
#pragma unroll
        for (int p = 0; p < BM / 32; p++) {
            int m = lrow + p * 32;
            const float* src = rowptr[m];
            float4 v = make_float4(0.f, 0.f, 0.f, 0.f);
            if (src)
                v = *(const float4*)(src + kt + lcol);
            uint4 t;
            t.x = f2tf32(v.x); t.y = f2tf32(v.y);
            t.z = f2tf32(v.z); t.w = f2tf32(v.w);
            *(uint4*)&As[m][lcol] = t;
        }
#pragma unroll
        for (int p = 0; p < BN / 32; p++) {
            int n = lrow + p * 32;
            float4 v = make_float4(0.f, 0.f, 0.f, 0.f);
            if (n0 + n < N)
                v = *(const float4*)(W + (size_t)(n0 + n) * DIM + kt + lcol);
            uint4 t;
            t.x = f2tf32(v.x); t.y = f2tf32(v.y);
            t.z = f2tf32(v.z); t.w = f2tf32(v.w);
            *(uint4*)&Bs[n][lcol] = t;
        }
        __syncthreads();

#pragma unroll
        for (int ks = 0; ks < BK / 8; ks++) {
            uint32_t af[4][4], bf[4][2];
#pragma unroll
            for (int i = 0; i < 4; i++) {
                int mr = wm * 64 + i * 16;
                af[i][0] = As[mr + grp    ][ks * 8 + qid    ];
                af[i][1] = As[mr + grp + 8][ks * 8 + qid    ];
                af[i][2] = As[mr + grp    ][ks * 8 + qid + 4];
                af[i][3] = As[mr + grp + 8][ks * 8 + qid + 4];
            }
#pragma unroll
            for (int j = 0; j < 4; j++) {
                int nr = wn * 32 + j * 8;
                bf[j][0] = Bs[nr + grp][ks * 8 + qid    ];
                bf[j][1] = Bs[nr + grp][ks * 8 + qid + 4];
            }
#pragma unroll
            for (int i = 0; i < 4; i++)
#pragma unroll
                for (int j = 0; j < 4; j++)
                    mma_tf32(acc[i][j], af[i], bf[j]);
        }
        __syncthreads();
    }

#pragma unroll
    for (int i = 0; i < 4; i++) {
#pragma unroll
        for (int j = 0; j < 4; j++) {
            int m = m0 + wm * 64 + i * 16 + grp;
            int n = n0 + wn * 32 + j * 8 + qid * 2;
            if (n < N) {
                float bb0 = c1[n] + c2[n];
                float bb1 = c1[n + 1] + c2[n + 1];
                C[(size_t)m * G4 + n]           = acc[i][j][0] + bb0;
                C[(size_t)m * G4 + n + 1]       = acc[i][j][1] + bb1;
                C[(size_t)(m + 8) * G4 + n]     = acc[i][j][2] + bb0;
                C[(size_t)(m + 8) * G4 + n + 1] = acc[i][j][3] + bb1;
            }
        }
    }
}

// ---------------------------------------------------------------------------
// Fused hh GEMM + cell on ACTIVE PREFIX (spans sorted by len desc).
// BM=64 positions, BN=64 = 4 gates x 16 hh. h double-buffered by parity.
// Blocks with m0 >= act[t] exit immediately.
// grid = (13, 20, 2)
// ---------------------------------------------------------------------------
__global__ __launch_bounds__(256)
void gemm_hh_cell_kernel(const float* __restrict__ Wf, const float* __restrict__ Wb,
                         const int* __restrict__ slen, int t)
{
    const int BM = 64, BN = 64, K = H;
    int m0 = blockIdx.y * BM;
    if (m0 >= d_act[t]) return;

    __shared__ uint32_t As[BM][LDSROW];
    __shared__ uint32_t Bs[BN][LDSROW];
    __shared__ float Gs[BM][BN + 4];
    __shared__ int   xrow[BM];
    __shared__ int   lens[BM];
    __shared__ int   orign[BM];

    int dir = blockIdx.z;
    const float* A     = d_h + ((t - 1) & 1) * HBUF + (size_t)dir * NSPANS * H;
    float*       h_out = d_h + (t & 1) * HBUF;
    const float* W  = dir ? Wb : Wf;
    const float* XG = d_xg + (size_t)dir * MROWS * G4;

    int tid  = threadIdx.x;
    int warp = tid >> 5, lane = tid & 31;
    int wm = warp & 1, wn = warp >> 1;
    int grp = lane >> 2, qid = lane & 3;
    int hh_base = blockIdx.x * 16;

    if (tid < BM) {
        int n  = d_sorted[m0 + tid];
        int ln = slen[n];
        lens[tid]  = ln;
        orign[tid] = n;
        int tt = t < ln ? t : (ln - 1);
        xrow[tid] = d_offset[n] + tt;
    }

    float acc[2][2][4];
#pragma unroll
    for (int i = 0; i < 2; i++)
#pragma unroll
        for (int j = 0; j < 2; j++)
#pragma unroll
            for (int q = 0; q < 4; q++) acc[i][j][q] = 0.f;

    const int lrow = tid >> 3;
    const int lcol = (tid & 7) * 4;

    for (int kt = 0; kt < K; kt += BK) {
#pragma unroll
        for (int p = 0; p < BM / 32; p++) {
            int m = lrow + p * 32;
            int k = kt + lcol;
            float4 v = make_float4(0.f, 0.f, 0.f, 0.f);
            if (k < K)
                v = *(const float4*)(A + (size_t)(m0 + m) * H + k);
            uint4 tt;
            tt.x = f2tf32(v.x); tt.y = f2tf32(v.y);
            tt.z = f2tf32(v.z); tt.w = f2tf32(v.w);
            *(uint4*)&As[m][lcol] = tt;
        }
#pragma unroll
        for (int p = 0; p < BN / 32; p++) {
            int n = lrow + p * 32;
            int hhi = hh_base + (n & 15);
            int grow = (n >> 4) * H + hhi;
            int k = kt + lcol;
            float4 v = make_float4(0.f, 0.f, 0.f, 0.f);
            if (hhi < H && k < K)
                v = *(const float4*)(W + (size_t)grow * H + k);
            uint4 tt;
            tt.x = f2tf32(v.x); tt.y = f2tf32(v.y);
            tt.z = f2tf32(v.z); tt.w = f2tf32(v.w);
            *(uint4*)&Bs[n][lcol] = tt;
        }
        __syncthreads();

#pragma unroll
        for (int ks = 0; ks < BK / 8; ks++) {
            uint32_t af[2][4], bf[2][2];
#pragma unroll
            for (int i = 0; i < 2; i++) {
                int mr = wm * 32 + i * 16;
                af[i][0] = As[mr + grp    ][ks * 8 + qid    ];
                af[i][1] = As[mr + grp + 8][ks * 8 + qid    ];
                af[i][2] = As[mr + grp    ][ks * 8 + qid + 4];
                af[i][3] = As[mr + grp + 8][ks * 8 + qid + 4];
            }
#pragma unroll
            for (int j = 0; j < 2; j++) {
                int nr = wn * 16 + j * 8;
                bf[j][0] = Bs[nr + grp][ks * 8 + qid    ];
                bf[j][1] = Bs[nr + grp][ks * 8 + qid + 4];
            }
#pragma unroll
            for (int i = 0; i < 2; i++)
#pragma unroll
                for (int j = 0; j < 2; j++)
                    mma_tf32(acc[i][j], af[i], bf[j]);
        }
        __syncthreads();
    }

    // Stage gate tile
#pragma unroll
    for (int i = 0; i < 2; i++) {
#pragma unroll
        for (int j = 0; j < 2; j++) {
            int m = wm * 32 + i * 16 + grp;
            int n = wn * 16 + j * 8 + qid * 2;
            Gs[m][n]         = acc[i][j][0];
            Gs[m][n + 1]     = acc[i][j][1];
            Gs[m + 8][n]     = acc[i][j][2];
            Gs[m + 8][n + 1] = acc[i][j][3];
        }
    }
    __syncthreads();

    // Cell phase: 64x16 items, 4 per thread
#pragma unroll
    for (int it = 0; it < 4; it++) {
        int id = tid + it * 256;
        int m  = id >> 4;
        int hl = id & 15;
        int hhi = hh_base + hl;
        if (hhi >= H) continue;

        size_t xb = (size_t)xrow[m] * G4 + hhi;
        float gi = Gs[m][hl     ] + XG[xb];
        float gf = Gs[m][16 + hl] + XG[xb + H];
        float gg = Gs[m][32 + hl] + XG[xb + 2 * H];
        float go = Gs[m][48 + hl] + XG[xb + 3 * H];

        size_t pidx = (size_t)dir * NSPANS * H + (size_t)(m0 + m) * H + hhi;
        float cn = sigm(gf) * d_c[pidx] + sigm(gi) * tanhf(gg);
        float hn = sigm(go) * tanhf(cn);
        d_c[pidx]   = cn;
        h_out[pidx] = hn;
        if (t < lens[m])
            d_sum[(size_t)dir * NSPANS * H + (size_t)orign[m] * H + hhi] += hn;
    }
}

// ---------------------------------------------------------------------------
// t=0 cell by sorted position: gates = xg[offset[n]] (h=0).
// ---------------------------------------------------------------------------
__global__ void lstm_cell0(const int* __restrict__ slen)
{
    int idx = blockIdx.x * blockDim.x + threadIdx.x;
    if (idx >= 2 * NSPANS * H) return;
    int hh  = idx % H;
    int pos = (idx / H) % NSPANS;
    int dir = idx / (H * NSPANS);
    int n   = d_sorted[pos];

    int row = d_offset[n];
    const float* g = d_xg + (size_t)dir * MROWS * G4 + (size_t)row * G4;
    float gi = g[hh];
    float gg = g[2 * H + hh];
    float go = g[3 * H + hh];

    float cn = sigm(gi) * tanhf(gg);
    float hn = sigm(go) * tanhf(cn);
    d_c[idx] = cn;          // pos-indexed
    d_h[idx] = hn;          // parity 0, pos-indexed
    d_sum[(size_t)dir * NSPANS * H + (size_t)n * H + hh] = hn;  // slen >= 1
}

// ---------------------------------------------------------------------------
// Logits with smem-staged E. 512 threads = 32 spans x 16 ents. grid = 40.
// ---------------------------------------------------------------------------
__global__ __launch_bounds__(512)
void logits_kernel(const float* __restrict__ E, float* __restrict__ out)
{
    __shared__ float Es[NENT * 2 * H];   // 25.6 KB
    int tid = threadIdx.x;
    for (int i = tid; i < NENT * 2 * H; i += 512)
        Es[i] = E[i];
    __syncthreads();

    int s = tid >> 4;
    int e = tid & 15;
    int n = blockIdx.x * 32 + s;

    const float4* sf = (const float4*)(d_sum + (size_t)n * H);
    const float4* sb = (const float4*)(d_sum + (size_t)NSPANS * H + (size_t)n * H);
    const float4* er = (const float4*)(Es + e * 2 * H);

    float acc = 0.f;
#pragma unroll
    for (int j = 0; j < H / 4; j++) {
        float4 a = sf[j], b = er[j];
        acc += a.x * b.x + a.y * b.y + a.z * b.z + a.w * b.w;
    }
#pragma unroll
    for (int j = 0; j < H / 4; j++) {
        float4 a = sb[j], b = er[H / 4 + j];
        acc += a.x * b.x + a.y * b.y + a.z * b.z + a.w * b.w;
    }
    out[n * NENT + e] = acc;
}

// ---------------------------------------------------------------------------
// Launch
// ---------------------------------------------------------------------------
extern "C" void kernel_launch(void* const* d_in, const int* in_sizes, int n_in,
                              void* d_out, int out_size)
{
    const float* hidden = (const float*)d_in[0];
    const int*   tok    = (const int*)d_in[1];
    const int*   slen   = (const int*)d_in[2];
    const int*   sbatch = (const int*)d_in[3];
    const float* W_ih_f = (const float*)d_in[4];
    const float* W_hh_f = (const float*)d_in[5];
    const float* b_ih_f = (const float*)d_in[6];
    const float* b_hh_f = (const float*)d_in[7];
    const float* W_ih_b = (const float*)d_in[8];
    const float* W_hh_b = (const float*)d_in[9];
    const float* b_ih_b = (const float*)d_in[10];
    const float* b_hh_b = (const float*)d_in[11];
    const float* E      = (const float*)d_in[12];
    float* out          = (float*)d_out;

    // 0. Compaction + length sort
    compact_kernel<<<1, 256>>>(slen);

    // 1. xg GEMM, fused gather, compacted rows: grid 7 x 50 x 2 (self-trim)
    {
        dim3 grid((G4 + 127) / 128, MROWS / 128, 2);
        gemm_xg_kernel<<<grid, 256>>>(hidden, tok, slen, sbatch,
                                      W_ih_f, b_ih_f, b_hh_f,
                                      W_ih_b, b_ih_b, b_hh_b);
    }

    // 2. Recurrence on sorted spans; steps shrink to active prefix
    {
        const int ct = 256;
        lstm_cell0<<<(2 * NSPANS * H + ct - 1) / ct, ct>>>(slen);
    }
    for (int t = 1; t < LMAX; t++) {
        dim3 grid((H + 15) / 16, NSPANS / 64, 2);   // 13 x 20 x 2, blocks self-trim
        gemm_hh_cell_kernel<<<grid, 256>>>(W_hh_f, W_hh_b, slen, t);
    }

    // 3. Logits
    logits_kernel<<<NSPANS / 32, 512>>>(E, out);
}

// round 12
// speedup vs baseline: 1.8903x; 1.0763x over previous
#include <cuda_runtime.h>
#include <math.h>
#include <stdint.h>

// Problem constants
#define BSZ 64
#define SEQ 512
#define DIM 768
#define NSPANS 1280
#define LMAX 5
#define H 200
#define G4 800          // 4*H
#define NENT 16
#define MROWS (NSPANS*LMAX)   // 6400

// Scratch (device globals)
__device__ float d_xg    [2ll * MROWS * G4];
__device__ float d_h     [2ll * 2 * NSPANS * H];   // [parity][dir][n][hh], tf32-rounded
__device__ float d_c     [2ll * NSPANS * H];
__device__ float d_sum   [2ll * NSPANS * H];
__device__ float d_whh   [2ll * G4 * H];           // pre-tf32-rounded W_hh per dir
__device__ int   d_offset[NSPANS + 1];
__device__ int   d_rowmap[MROWS];

#define HBUF (2ll * NSPANS * H)

// ---------------------------------------------------------------------------
// tf32 / mma / cp.async helpers
// ---------------------------------------------------------------------------
__device__ __forceinline__ uint32_t f2tf32(float f) {
    uint32_t r;
    asm("cvt.rna.tf32.f32 %0, %1;" : "=r"(r) : "f"(f));
    return r;
}

__device__ __forceinline__ void mma_tf32(float* c, const uint32_t* a, const uint32_t* b) {
    asm volatile(
        "mma.sync.aligned.m16n8k8.row.col.f32.tf32.tf32.f32 "
        "{%0,%1,%2,%3}, {%4,%5,%6,%7}, {%8,%9}, {%0,%1,%2,%3};"
        : "+f"(c[0]), "+f"(c[1]), "+f"(c[2]), "+f"(c[3])
        : "r"(a[0]), "r"(a[1]), "r"(a[2]), "r"(a[3]), "r"(b[0]), "r"(b[1]));
}

__device__ __forceinline__ float sigm(float x) { return 1.f / (1.f + expf(-x)); }

__device__ __forceinline__ uint32_t smem_u32(const void* p) {
    return (uint32_t)__cvta_generic_to_shared(p);
}

__device__ __forceinline__ void cp_async16(uint32_t dst, const void* src, int src_bytes) {
    asm volatile("cp.async.ca.shared.global [%0], [%1], 16, %2;"
                 :: "r"(dst), "l"(src), "r"(src_bytes));
}
__device__ __forceinline__ void cp_commit() {
    asm volatile("cp.async.commit_group;");
}
template <int N>
__device__ __forceinline__ void cp_wait() {
    asm volatile("cp.async.wait_group %0;" :: "n"(N));
}

#define BK 32
#define PAD 4
#define LDSROW (BK + PAD)   // 36 uints per row (proven layout)

// ---------------------------------------------------------------------------
// Prep: pre-round W_hh (both dirs) to tf32-valued fp32
// ---------------------------------------------------------------------------
__global__ void whh_prep_kernel(const float* __restrict__ Wf,
                                const float* __restrict__ Wb)
{
    int i = blockIdx.x * blockDim.x + threadIdx.x;
    if (i < G4 * H) {
        d_whh[i]           = __uint_as_float(f2tf32(Wf[i]));
        d_whh[G4 * H + i]  = __uint_as_float(f2tf32(Wb[i]));
    }
}

// ---------------------------------------------------------------------------
// Compaction: offsets = exclusive-prefix(slen); rowmap[off+l] = (n<<3)|l
// ---------------------------------------------------------------------------
__global__ void compact_kernel(const int* __restrict__ slen)
{
    __shared__ int part[256];
    int tid = threadIdx.x;
    int base = tid * 5;
    int loc[5], s = 0;
#pragma unroll
    for (int i = 0; i < 5; i++) { loc[i] = s; s += slen[base + i]; }
    part[tid] = s;
    __syncthreads();
    for (int off = 1; off < 256; off <<= 1) {
        int v = (tid >= off) ? part[tid - off] : 0;
        __syncthreads();
        part[tid] += v;
        __syncthreads();
    }
    int pre = (tid == 0) ? 0 : part[tid - 1];
#pragma unroll
    for (int i = 0; i < 5; i++) {
        int n = base + i;
        int off = pre + loc[i];
        d_offset[n] = off;
        int ln = slen[n];
        for (int l = 0; l < ln; l++)
            d_rowmap[off + l] = (n << 3) | l;
    }
    if (tid == 255) d_offset[NSPANS] = part[255];
}

// ---------------------------------------------------------------------------
// xg GEMM, fused gather, compacted rows (R8 proven: BM=128, BN=64)
// ---------------------------------------------------------------------------
__global__ __launch_bounds__(256)
void gemm_xg_kernel(const float* __restrict__ hidden,
                    const int* __restrict__ tok,
                    const int* __restrict__ slen,
                    const int* __restrict__ sbatch,
                    const float* __restrict__ Wf, const float* __restrict__ bif,
                    const float* __restrict__ bhf,
                    const float* __restrict__ Wb, const float* __restrict__ bib,
                    const float* __restrict__ bhb)
{
    const int BM = 128, BN = 64, K = DIM, N = G4;
    int m0 = blockIdx.y * BM;
    int count = d_offset[NSPANS];
    if (m0 >= count) return;

    __shared__ uint32_t As[BM][LDSROW];
    __shared__ uint32_t Bs[BN][LDSROW];
    __shared__ const float* rowptr[BM];

    int dir = blockIdx.z;
    const float* W  = dir ? Wb : Wf;
    const float* c1 = dir ? bib : bif;
    const float* c2 = dir ? bhb : bhf;
    float* C        = d_xg + (size_t)dir * MROWS * G4;

    int tid  = threadIdx.x;
    int warp = tid >> 5, lane = tid & 31;
    int wm = warp & 3, wn = warp >> 2;
    int grp = lane >> 2, qid = lane & 3;
    int n0 = blockIdx.x * BN;

    if (tid < BM) {
        int r = m0 + tid;
        const float* p = nullptr;
        if (r < count) {
            int rm = d_rowmap[r];
            int n  = rm >> 3;
            int l  = rm & 7;
            int ln = slen[n];
            int sl = dir ? (ln - 1 - l) : l;
            int t  = tok[n * LMAX + sl];
            int b  = sbatch[n];
            p = hidden + ((size_t)b * SEQ + t) * DIM;
        }
        rowptr[tid] = p;
    }
    __syncthreads();

    float acc[2][4][4];
#pragma unroll
    for (int i = 0; i < 2; i++)
#pragma unroll
        for (int j = 0; j < 4; j++)
#pragma unroll
            for (int q = 0; q < 4; q++) acc[i][j][q] = 0.f;

    const int lrow = tid >> 3;
    const int lcol = (tid & 7) * 4;

    for (int kt = 0; kt < K; kt += BK) {
#pragma unroll
        for (int p = 0; p < BM / 32; p++) {
            int m = lrow + p * 32;
            const float* src = rowptr[m];
            float4 v = make_float4(0.f, 0.f, 0.f, 0.f);
            if (src)
                v = *(const float4*)(src + kt + lcol);
            uint4 t;
            t.x = f2tf32(v.x); t.y = f2tf32(v.y);
            t.z = f2tf32(v.z); t.w = f2tf32(v.w);
            *(uint4*)&As[m][lcol] = t;
        }
#pragma unroll
        for (int p = 0; p < BN / 32; p++) {
            int n = lrow + p * 32;
            float4 v = make_float4(0.f, 0.f, 0.f, 0.f);
            if (n0 + n < N)
                v = *(const float4*)(W + (size_t)(n0 + n) * DIM + kt + lcol);
            uint4 t;
            t.x = f2tf32(v.x); t.y = f2tf32(v.y);
            t.z = f2tf32(v.z); t.w = f2tf32(v.w);
            *(uint4*)&Bs[n][lcol] = t;
        }
        __syncthreads();

#pragma unroll
        for (int ks = 0; ks < BK / 8; ks++) {
            uint32_t af[2][4], bf[4][2];
#pragma unroll
            for (int i = 0; i < 2; i++) {
                int mr = wm * 32 + i * 16;
                af[i][0] = As[mr + grp    ][ks * 8 + qid    ];
                af[i][1] = As[mr + grp + 8][ks * 8 + qid    ];
                af[i][2] = As[mr + grp    ][ks * 8 + qid + 4];
                af[i][3] = As[mr + grp + 8][ks * 8 + qid + 4];
            }
#pragma unroll
            for (int j = 0; j < 4; j++) {
                int nr = wn * 32 + j * 8;
                bf[j][0] = Bs[nr + grp][ks * 8 + qid    ];
                bf[j][1] = Bs[nr + grp][ks * 8 + qid + 4];
            }
#pragma unroll
            for (int i = 0; i < 2; i++)
#pragma unroll
                for (int j = 0; j < 4; j++)
                    mma_tf32(acc[i][j], af[i], bf[j]);
        }
        __syncthreads();
    }

#pragma unroll
    for (int i = 0; i < 2; i++) {
#pragma unroll
        for (int j = 0; j < 4; j++) {
            int m = m0 + wm * 32 + i * 16 + grp;
            int n = n0 + wn * 32 + j * 8 + qid * 2;
            if (n < N) {
                float bb0 = c1[n] + c2[n];
                float bb1 = c1[n + 1] + c2[n + 1];
                C[(size_t)m * G4 + n]           = acc[i][j][0] + bb0;
                C[(size_t)m * G4 + n + 1]       = acc[i][j][1] + bb1;
                C[(size_t)(m + 8) * G4 + n]     = acc[i][j][2] + bb0;
                C[(size_t)(m + 8) * G4 + n + 1] = acc[i][j][3] + bb1;
            }
        }
    }
}

// ---------------------------------------------------------------------------
// Fused hh GEMM + cell with cp.async double-buffering.
// A = h (tf32-rounded), B = d_whh (tf32-rounded) — raw 16B copies, no cvt.
// B-tile N-mapping (R8): local col n -> W row (n>>4)*H + hh_base + (n&15),
// hh_base = blockIdx.x * 16.  BM=64 spans, 8 warps (2Mx4N), warp tile 32x16.
// grid = (13, 20, 2)
// ---------------------------------------------------------------------------
#define NKT 7   // ceil(200/32)

__global__ __launch_bounds__(256)
void gemm_hh_cell_kernel(const int* __restrict__ slen, int t)
{
    const int BM = 64, BN = 64, K = H;

    __shared__ uint32_t TileA[2 * BM * LDSROW];   // 18432 B
    __shared__ uint32_t TileB[2 * BN * LDSROW];   // 18432 B
    float* Gs = (float*)TileA;                    // alias: used after mainloop, [BM][68]
    __shared__ int xrow[BM];
    __shared__ int lens[BM];

    int dir = blockIdx.z;
    const float* A     = d_h + ((t - 1) & 1) * HBUF + (size_t)dir * NSPANS * H;
    float*       h_out = d_h + (t & 1) * HBUF;
    const float* W  = d_whh + (size_t)dir * G4 * H;
    const float* XG = d_xg + (size_t)dir * MROWS * G4;

    int tid  = threadIdx.x;
    int warp = tid >> 5, lane = tid & 31;
    int wm = warp & 1, wn = warp >> 1;
    int grp = lane >> 2, qid = lane & 3;
    int m0 = blockIdx.y * BM;
    int hh_base = blockIdx.x * 16;

    if (tid < BM) {
        int n  = m0 + tid;
        int ln = slen[n];
        lens[tid] = ln;
        int tt = t < ln ? t : (ln - 1);
        xrow[tid] = d_offset[n] + tt;
    }

    uint32_t sA = smem_u32(TileA);
    uint32_t sB = smem_u32(TileB);

    // tile loader: 2 chunks (rows) per thread per matrix
    auto load_tile = [&](int buf, int kt) {
#pragma unroll
        for (int it = 0; it < 2; it++) {
            int c   = tid + it * 256;
            int row = c >> 3, c4 = c & 7;
            int k   = kt + c4 * 4;
            int remb = (K - k) * 4;
            int sz  = remb < 0 ? 0 : (remb > 16 ? 16 : remb);
            // A: span rows always valid
            {
                const float* src = A + (size_t)(m0 + row) * H + (sz ? k : 0);
                cp_async16(sA + ((buf * BM + row) * LDSROW + c4 * 4) * 4, src, sz);
            }
            // B: remapped gate/hh row; zero-fill when hh out of range
            {
                int hhi  = hh_base + (row & 15);
                int gn   = (row >> 4) * H + hhi;
                int szb  = (hhi < H) ? sz : 0;
                const float* src = W + (szb ? ((size_t)gn * H + k) : 0);
                cp_async16(sB + ((buf * BN + row) * LDSROW + c4 * 4) * 4, src, szb);
            }
        }
        cp_commit();
    };

    float acc[2][2][4];
#pragma unroll
    for (int i = 0; i < 2; i++)
#pragma unroll
        for (int j = 0; j < 2; j++)
#pragma unroll
            for (int q = 0; q < 4; q++) acc[i][j][q] = 0.f;

    load_tile(0, 0);

    for (int i = 0; i < NKT; i++) {
        if (i + 1 < NKT) {
            load_tile((i + 1) & 1, (i + 1) * BK);
            cp_wait<1>();
        } else {
            cp_wait<0>();
        }
        __syncthreads();

        const uint32_t* Ab = TileA + (i & 1) * BM * LDSROW;
        const uint32_t* Bb = TileB + (i & 1) * BN * LDSROW;

#pragma unroll
        for (int ks = 0; ks < BK / 8; ks++) {
            uint32_t af[2][4], bf[2][2];
#pragma unroll
            for (int ii = 0; ii < 2; ii++) {
                int mr = wm * 32 + ii * 16;
                af[ii][0] = Ab[(mr + grp    ) * LDSROW + ks * 8 + qid    ];
                af[ii][1] = Ab[(mr + grp + 8) * LDSROW + ks * 8 + qid    ];
                af[ii][2] = Ab[(mr + grp    ) * LDSROW + ks * 8 + qid + 4];
                af[ii][3] = Ab[(mr + grp + 8) * LDSROW + ks * 8 + qid + 4];
            }
#pragma unroll
            for (int j = 0; j < 2; j++) {
                int nr = wn * 16 + j * 8;
                bf[j][0] = Bb[(nr + grp) * LDSROW + ks * 8 + qid    ];
                bf[j][1] = Bb[(nr + grp) * LDSROW + ks * 8 + qid + 4];
            }
#pragma unroll
            for (int ii = 0; ii < 2; ii++)
#pragma unroll
                for (int j = 0; j < 2; j++)
                    mma_tf32(acc[ii][j], af[ii], bf[j]);
        }
        __syncthreads();
    }

    // Stage gate tile into aliased Gs (all mainloop reads complete)
#pragma unroll
    for (int i = 0; i < 2; i++) {
#pragma unroll
        for (int j = 0; j < 2; j++) {
            int m = wm * 32 + i * 16 + grp;
            int n = wn * 16 + j * 8 + qid * 2;
            Gs[m * 68 + n]           = acc[i][j][0];
            Gs[m * 68 + n + 1]       = acc[i][j][1];
            Gs[(m + 8) * 68 + n]     = acc[i][j][2];
            Gs[(m + 8) * 68 + n + 1] = acc[i][j][3];
        }
    }
    __syncthreads();

    // Cell phase: 64 spans x 16 hh, 4 items per thread
#pragma unroll
    for (int it = 0; it < 4; it++) {
        int id = tid + it * 256;
        int m  = id >> 4;
        int hl = id & 15;
        int hhi = hh_base + hl;
        if (hhi >= H) continue;

        size_t xb = (size_t)xrow[m] * G4 + hhi;
        float gi = Gs[m * 68 + hl     ] + XG[xb];
        float gf = Gs[m * 68 + 16 + hl] + XG[xb + H];
        float gg = Gs[m * 68 + 32 + hl] + XG[xb + 2 * H];
        float go = Gs[m * 68 + 48 + hl] + XG[xb + 3 * H];

        size_t sidx = (size_t)dir * NSPANS * H + (size_t)(m0 + m) * H + hhi;
        float cn = sigm(gf) * d_c[sidx] + sigm(gi) * tanhf(gg);
        float hn = sigm(go) * tanhf(cn);
        d_c[sidx] = cn;
        h_out[sidx] = __uint_as_float(f2tf32(hn));
        if (t < lens[m]) d_sum[sidx] += hn;
    }
}

// ---------------------------------------------------------------------------
// t=0 cell: gates = xg[offset[n]] (h=0). h stored tf32-rounded, parity 0.
// ---------------------------------------------------------------------------
__global__ void lstm_cell0(const int* __restrict__ slen)
{
    int idx = blockIdx.x * blockDim.x + threadIdx.x;
    if (idx >= 2 * NSPANS * H) return;
    int hh  = idx % H;
    int n   = (idx / H) % NSPANS;
    int dir = idx / (H * NSPANS);

    int row = d_offset[n];
    const float* g = d_xg + (size_t)dir * MROWS * G4 + (size_t)row * G4;
    float gi = g[hh];
    float gg = g[2 * H + hh];
    float go = g[3 * H + hh];

    float cn = sigm(gi) * tanhf(gg);
    float hn = sigm(go) * tanhf(cn);
    d_c[idx] = cn;
    d_h[idx] = __uint_as_float(f2tf32(hn));   // parity 0
    d_sum[idx] = hn;
}

// ---------------------------------------------------------------------------
// Logits with smem-staged E. 512 threads, 32 spans x 16 ents. grid = 40.
// ---------------------------------------------------------------------------
__global__ __launch_bounds__(512)
void logits_kernel(const float* __restrict__ E, float* __restrict__ out)
{
    __shared__ float Es[NENT * 2 * H];
    int tid = threadIdx.x;
    for (int i = tid; i < NENT * 2 * H; i += 512)
        Es[i] = E[i];
    __syncthreads();

    int s = tid >> 4;
    int e = tid & 15;
    int n = blockIdx.x * 32 + s;

    const float4* sf = (const float4*)(d_sum + (size_t)n * H);
    const float4* sb = (const float4*)(d_sum + (size_t)NSPANS * H + (size_t)n * H);
    const float4* er = (const float4*)(Es + e * 2 * H);

    float acc = 0.f;
#pragma unroll
    for (int j = 0; j < H / 4; j++) {
        float4 a = sf[j], b = er[j];
        acc += a.x * b.x + a.y * b.y + a.z * b.z + a.w * b.w;
    }
#pragma unroll
    for (int j = 0; j < H / 4; j++) {
        float4 a = sb[j], b = er[H / 4 + j];
        acc += a.x * b.x + a.y * b.y + a.z * b.z + a.w * b.w;
    }
    out[n * NENT + e] = acc;
}

// ---------------------------------------------------------------------------
// Launch
// ---------------------------------------------------------------------------
extern "C" void kernel_launch(void* const* d_in, const int* in_sizes, int n_in,
                              void* d_out, int out_size)
{
    const float* hidden = (const float*)d_in[0];
    const int*   tok    = (const int*)d_in[1];
    const int*   slen   = (const int*)d_in[2];
    const int*   sbatch = (const int*)d_in[3];
    const float* W_ih_f = (const float*)d_in[4];
    const float* W_hh_f = (const float*)d_in[5];
    const float* b_ih_f = (const float*)d_in[6];
    const float* b_hh_f = (const float*)d_in[7];
    const float* W_ih_b = (const float*)d_in[8];
    const float* W_hh_b = (const float*)d_in[9];
    const float* b_ih_b = (const float*)d_in[10];
    const float* b_hh_b = (const float*)d_in[11];
    const float* E      = (const float*)d_in[12];
    float* out          = (float*)d_out;

    // 0. Compaction + W_hh tf32 pre-round
    compact_kernel<<<1, 256>>>(slen);
    whh_prep_kernel<<<(G4 * H + 255) / 256, 256>>>(W_hh_f, W_hh_b);

    // 1. xg GEMM, fused gather, compacted rows: grid 13 x 50 x 2 (self-trim)
    {
        dim3 grid((G4 + 63) / 64, MROWS / 128, 2);
        gemm_xg_kernel<<<grid, 256>>>(hidden, tok, slen, sbatch,
                                      W_ih_f, b_ih_f, b_hh_f,
                                      W_ih_b, b_ih_b, b_hh_b);
    }

    // 2. Recurrence
    {
        const int ct = 256;
        lstm_cell0<<<(2 * NSPANS * H + ct - 1) / ct, ct>>>(slen);
    }
    for (int t = 1; t < LMAX; t++) {
        dim3 grid((H + 15) / 16, NSPANS / 64, 2);   // 13 x 20 x 2
        gemm_hh_cell_kernel<<<grid, 256>>>(slen, t);
    }

    // 3. Logits
    logits_kernel<<<NSPANS / 32, 512>>>(E, out);
}

// round 13
// speedup vs baseline: 1.8910x; 1.0004x over previous
#include <cuda_runtime.h>
#include <math.h>
#include <stdint.h>

// Problem constants
#define BSZ 64
#define SEQ 512
#define DIM 768
#define NSPANS 1280
#define LMAX 5
#define H 200
#define G4 800          // 4*H
#define NENT 16
#define MROWS (NSPANS*LMAX)   // 6400

// Scratch (device globals)
__device__ float d_xg    [2ll * MROWS * G4];
__device__ float d_h     [2ll * 2 * NSPANS * H];   // [parity][dir][n][hh]
__device__ float d_c     [2ll * NSPANS * H];
__device__ float d_sum   [2ll * NSPANS * H];
__device__ int   d_offset[NSPANS + 1];
__device__ int   d_rowmap[MROWS];

#define HBUF (2ll * NSPANS * H)

// ---------------------------------------------------------------------------
// tf32 / mma / cp.async helpers
// ---------------------------------------------------------------------------
__device__ __forceinline__ uint32_t f2tf32(float f) {
    uint32_t r;
    asm("cvt.rna.tf32.f32 %0, %1;" : "=r"(r) : "f"(f));
    return r;
}

__device__ __forceinline__ void mma_tf32(float* c, const uint32_t* a, const uint32_t* b) {
    asm volatile(
        "mma.sync.aligned.m16n8k8.row.col.f32.tf32.tf32.f32 "
        "{%0,%1,%2,%3}, {%4,%5,%6,%7}, {%8,%9}, {%0,%1,%2,%3};"
        : "+f"(c[0]), "+f"(c[1]), "+f"(c[2]), "+f"(c[3])
        : "r"(a[0]), "r"(a[1]), "r"(a[2]), "r"(a[3]), "r"(b[0]), "r"(b[1]));
}

__device__ __forceinline__ float sigm(float x) { return 1.f / (1.f + expf(-x)); }

__device__ __forceinline__ uint32_t smem_u32(const void* p) {
    return (uint32_t)__cvta_generic_to_shared(p);
}

__device__ __forceinline__ void cp_async16(uint32_t dst, const void* src, int src_bytes) {
    asm volatile("cp.async.ca.shared.global [%0], [%1], 16, %2;"
                 :: "r"(dst), "l"(src), "r"(src_bytes));
}
__device__ __forceinline__ void cp_commit() {
    asm volatile("cp.async.commit_group;");
}
template <int N>
__device__ __forceinline__ void cp_wait() {
    asm volatile("cp.async.wait_group %0;" :: "n"(N));
}

#define BK 32
#define PAD 4
#define LDSROW (BK + PAD)   // 36 uints per row (proven layout)

// ---------------------------------------------------------------------------
// Compaction: offsets = exclusive-prefix(slen); rowmap[off+l] = (n<<3)|l
// ---------------------------------------------------------------------------
__global__ void compact_kernel(const int* __restrict__ slen)
{
    __shared__ int part[256];
    int tid = threadIdx.x;
    int base = tid * 5;
    int loc[5], s = 0;
#pragma unroll
    for (int i = 0; i < 5; i++) { loc[i] = s; s += slen[base + i]; }
    part[tid] = s;
    __syncthreads();
    for (int off = 1; off < 256; off <<= 1) {
        int v = (tid >= off) ? part[tid - off] : 0;
        __syncthreads();
        part[tid] += v;
        __syncthreads();
    }
    int pre = (tid == 0) ? 0 : part[tid - 1];
#pragma unroll
    for (int i = 0; i < 5; i++) {
        int n = base + i;
        int off = pre + loc[i];
        d_offset[n] = off;
        int ln = slen[n];
        for (int l = 0; l < ln; l++)
            d_rowmap[off + l] = (n << 3) | l;
    }
    if (tid == 255) d_offset[NSPANS] = part[255];
}

// ---------------------------------------------------------------------------
// xg GEMM, fused gather, compacted rows (R8 proven: BM=128, BN=64)
// ---------------------------------------------------------------------------
__global__ __launch_bounds__(256)
void gemm_xg_kernel(const float* __restrict__ hidden,
                    const int* __restrict__ tok,
                    const int* __restrict__ slen,
                    const int* __restrict__ sbatch,
                    const float* __restrict__ Wf, const float* __restrict__ bif,
                    const float* __restrict__ bhf,
                    const float* __restrict__ Wb, const float* __restrict__ bib,
                    const float* __restrict__ bhb)
{
    const int BM = 128, BN = 64, K = DIM, N = G4;
    int m0 = blockIdx.y * BM;
    int count = d_offset[NSPANS];
    if (m0 >= count) return;

    __shared__ uint32_t As[BM][LDSROW];
    __shared__ uint32_t Bs[BN][LDSROW];
    __shared__ const float* rowptr[BM];

    int dir = blockIdx.z;
    const float* W  = dir ? Wb : Wf;
    const float* c1 = dir ? bib : bif;
    const float* c2 = dir ? bhb : bhf;
    float* C        = d_xg + (size_t)dir * MROWS * G4;

    int tid  = threadIdx.x;
    int warp = tid >> 5, lane = tid & 31;
    int wm = warp & 3, wn = warp >> 2;
    int grp = lane >> 2, qid = lane & 3;
    int n0 = blockIdx.x * BN;

    if (tid < BM) {
        int r = m0 + tid;
        const float* p = nullptr;
        if (r < count) {
            int rm = d_rowmap[r];
            int n  = rm >> 3;
            int l  = rm & 7;
            int ln = slen[n];
            int sl = dir ? (ln - 1 - l) : l;
            int t  = tok[n * LMAX + sl];
            int b  = sbatch[n];
            p = hidden + ((size_t)b * SEQ + t) * DIM;
        }
        rowptr[tid] = p;
    }
    __syncthreads();

    float acc[2][4][4];
#pragma unroll
    for (int i = 0; i < 2; i++)
#pragma unroll
        for (int j = 0; j < 4; j++)
#pragma unroll
            for (int q = 0; q < 4; q++) acc[i][j][q] = 0.f;

    const int lrow = tid >> 3;
    const int lcol = (tid & 7) * 4;

    for (int kt = 0; kt < K; kt += BK) {
#pragma unroll
        for (int p = 0; p < BM / 32; p++) {
            int m = lrow + p * 32;
            const float* src = rowptr[m];
            float4 v = make_float4(0.f, 0.f, 0.f, 0.f);
            if (src)
                v = *(const float4*)(src + kt + lcol);
            uint4 t;
            t.x = f2tf32(v.x); t.y = f2tf32(v.y);
            t.z = f2tf32(v.z); t.w = f2tf32(v.w);
            *(uint4*)&As[m][lcol] = t;
        }
#pragma unroll
        for (int p = 0; p < BN / 32; p++) {
            int n = lrow + p * 32;
            float4 v = make_float4(0.f, 0.f, 0.f, 0.f);
            if (n0 + n < N)
                v = *(const float4*)(W + (size_t)(n0 + n) * DIM + kt + lcol);
            uint4 t;
            t.x = f2tf32(v.x); t.y = f2tf32(v.y);
            t.z = f2tf32(v.z); t.w = f2tf32(v.w);
            *(uint4*)&Bs[n][lcol] = t;
        }
        __syncthreads();

#pragma unroll
        for (int ks = 0; ks < BK / 8; ks++) {
            uint32_t af[2][4], bf[4][2];
#pragma unroll
            for (int i = 0; i < 2; i++) {
                int mr = wm * 32 + i * 16;
                af[i][0] = As[mr + grp    ][ks * 8 + qid    ];
                af[i][1] = As[mr + grp + 8][ks * 8 + qid    ];
                af[i][2] = As[mr + grp    ][ks * 8 + qid + 4];
                af[i][3] = As[mr + grp + 8][ks * 8 + qid + 4];
            }
#pragma unroll
            for (int j = 0; j < 4; j++) {
                int nr = wn * 32 + j * 8;
                bf[j][0] = Bs[nr + grp][ks * 8 + qid    ];
                bf[j][1] = Bs[nr + grp][ks * 8 + qid + 4];
            }
#pragma unroll
            for (int i = 0; i < 2; i++)
#pragma unroll
                for (int j = 0; j < 4; j++)
                    mma_tf32(acc[i][j], af[i], bf[j]);
        }
        __syncthreads();
    }

#pragma unroll
    for (int i = 0; i < 2; i++) {
#pragma unroll
        for (int j = 0; j < 4; j++) {
            int m = m0 + wm * 32 + i * 16 + grp;
            int n = n0 + wn * 32 + j * 8 + qid * 2;
            if (n < N) {
                float bb0 = c1[n] + c2[n];
                float bb1 = c1[n + 1] + c2[n + 1];
                C[(size_t)m * G4 + n]           = acc[i][j][0] + bb0;
                C[(size_t)m * G4 + n + 1]       = acc[i][j][1] + bb1;
                C[(size_t)(m + 8) * G4 + n]     = acc[i][j][2] + bb0;
                C[(size_t)(m + 8) * G4 + n + 1] = acc[i][j][3] + bb1;
            }
        }
    }
}

// ---------------------------------------------------------------------------
// Fused hh GEMM + cell (R8 mainloop) + cp.async prefetch of cell operands.
// BM=64 spans, BN=64 = 4 gates x 16 hh; 8 warps (2Mx4N), warp tile 32x16.
// Gs aliases the tile buffers after the mainloop.
// grid = (13, 20, 2)
// ---------------------------------------------------------------------------
__global__ __launch_bounds__(256)
void gemm_hh_cell_kernel(const float* __restrict__ Wf, const float* __restrict__ Wb,
                         const int* __restrict__ slen, int t)
{
    const int BM = 64, BN = 64, K = H;

    __shared__ uint32_t Tiles[(BM + BN) * LDSROW];   // 18432 B; A then B
    float* Gs = (float*)Tiles;                       // alias after mainloop [BM][68]
    __shared__ float XGb [BM * 64];                  // 16 KB
    __shared__ float cbuf[BM * 16];                  // 4 KB
    __shared__ float sbuf[BM * 16];                  // 4 KB
    __shared__ int   xrow[BM];
    __shared__ int   lens[BM];

    uint32_t* As = Tiles;
    uint32_t* Bs = Tiles + BM * LDSROW;

    int dir = blockIdx.z;
    const float* A     = d_h + ((t - 1) & 1) * HBUF + (size_t)dir * NSPANS * H;
    float*       h_out = d_h + (t & 1) * HBUF;
    const float* W  = dir ? Wb : Wf;
    const float* XG = d_xg + (size_t)dir * MROWS * G4;

    int tid  = threadIdx.x;
    int warp = tid >> 5, lane = tid & 31;
    int wm = warp & 1, wn = warp >> 1;
    int grp = lane >> 2, qid = lane & 3;
    int m0 = blockIdx.y * BM;
    int hh_base = blockIdx.x * 16;

    if (tid < BM) {
        int n  = m0 + tid;
        int ln = slen[n];
        lens[tid] = ln;
        int tt = t < ln ? t : (ln - 1);
        xrow[tid] = d_offset[n] + tt;
    }
    __syncthreads();

    // ---- Prefetch cell operands (one async group, waits before cell phase)
    {
        uint32_t sXG = smem_u32(XGb);
        uint32_t sC  = smem_u32(cbuf);
        uint32_t sS  = smem_u32(sbuf);
        // XG gate slabs: 1024 chunks of 16B
#pragma unroll
        for (int it = 0; it < 4; it++) {
            int c = tid + it * 256;
            int m = c >> 4, g = (c >> 2) & 3, q = c & 3;
            int hh0 = hh_base + q * 4;
            int rem = (H - hh0) * 4;
            int sz  = rem < 0 ? 0 : (rem > 16 ? 16 : rem);
            const float* src = XG + (size_t)xrow[m] * G4 + g * H + (sz ? hh0 : 0);
            cp_async16(sXG + (uint32_t)(m * 64 + g * 16 + q * 4) * 4, src, sz);
        }
        // c and sum: 256 chunks each
        {
            int m = tid >> 2, q = tid & 3;
            int hh0 = hh_base + q * 4;
            int rem = (H - hh0) * 4;
            int sz  = rem < 0 ? 0 : (rem > 16 ? 16 : rem);
            size_t base = (size_t)dir * NSPANS * H + (size_t)(m0 + m) * H + (sz ? hh0 : 0);
            cp_async16(sC + (uint32_t)(m * 16 + q * 4) * 4, d_c + base, sz);
            cp_async16(sS + (uint32_t)(m * 16 + q * 4) * 4, d_sum + base, sz);
        }
        cp_commit();
    }

    float acc[2][2][4];
#pragma unroll
    for (int i = 0; i < 2; i++)
#pragma unroll
        for (int j = 0; j < 2; j++)
#pragma unroll
            for (int q = 0; q < 4; q++) acc[i][j][q] = 0.f;

    const int lrow = tid >> 3;
    const int lcol = (tid & 7) * 4;

    for (int kt = 0; kt < K; kt += BK) {
        // A tile
#pragma unroll
        for (int p = 0; p < BM / 32; p++) {
            int m = lrow + p * 32;
            int k = kt + lcol;
            float4 v = make_float4(0.f, 0.f, 0.f, 0.f);
            if (k < K)
                v = *(const float4*)(A + (size_t)(m0 + m) * H + k);
            uint4 tt;
            tt.x = f2tf32(v.x); tt.y = f2tf32(v.y);
            tt.z = f2tf32(v.z); tt.w = f2tf32(v.w);
            *(uint4*)&As[m * LDSROW + lcol] = tt;
        }
        // B tile: row map n -> (n>>4)*H + hh_base + (n&15)
#pragma unroll
        for (int p = 0; p < BN / 32; p++) {
            int n = lrow + p * 32;
            int hhi = hh_base + (n & 15);
            int grow = (n >> 4) * H + hhi;
            int k = kt + lcol;
            float4 v = make_float4(0.f, 0.f, 0.f, 0.f);
            if (hhi < H && k < K)
                v = *(const float4*)(W + (size_t)grow * H + k);
            uint4 tt;
            tt.x = f2tf32(v.x); tt.y = f2tf32(v.y);
            tt.z = f2tf32(v.z); tt.w = f2tf32(v.w);
            *(uint4*)&Bs[n * LDSROW + lcol] = tt;
        }
        __syncthreads();

#pragma unroll
        for (int ks = 0; ks < BK / 8; ks++) {
            uint32_t af[2][4], bf[2][2];
#pragma unroll
            for (int i = 0; i < 2; i++) {
                int mr = wm * 32 + i * 16;
                af[i][0] = As[(mr + grp    ) * LDSROW + ks * 8 + qid    ];
                af[i][1] = As[(mr + grp + 8) * LDSROW + ks * 8 + qid    ];
                af[i][2] = As[(mr + grp    ) * LDSROW + ks * 8 + qid + 4];
                af[i][3] = As[(mr + grp + 8) * LDSROW + ks * 8 + qid + 4];
            }
#pragma unroll
            for (int j = 0; j < 2; j++) {
                int nr = wn * 16 + j * 8;
                bf[j][0] = Bs[(nr + grp) * LDSROW + ks * 8 + qid    ];
                bf[j][1] = Bs[(nr + grp) * LDSROW + ks * 8 + qid + 4];
            }
#pragma unroll
            for (int i = 0; i < 2; i++)
#pragma unroll
                for (int j = 0; j < 2; j++)
                    mma_tf32(acc[i][j], af[i], bf[j]);
        }
        __syncthreads();
    }

    // Stage gate tile into aliased Gs (tile reads complete after last sync)
#pragma unroll
    for (int i = 0; i < 2; i++) {
#pragma unroll
        for (int j = 0; j < 2; j++) {
            int m = wm * 32 + i * 16 + grp;
            int n = wn * 16 + j * 8 + qid * 2;
            Gs[m * 68 + n]           = acc[i][j][0];
            Gs[m * 68 + n + 1]       = acc[i][j][1];
            Gs[(m + 8) * 68 + n]     = acc[i][j][2];
            Gs[(m + 8) * 68 + n + 1] = acc[i][j][3];
        }
    }
    cp_wait<0>();
    __syncthreads();

    // Cell phase: 64 spans x 16 hh, 4 items per thread — all smem reads
#pragma unroll
    for (int it = 0; it < 4; it++) {
        int id = tid + it * 256;
        int m  = id >> 4;
        int hl = id & 15;
        int hhi = hh_base + hl;
        if (hhi >= H) continue;

        float gi = Gs[m * 68 + hl     ] + XGb[m * 64 + hl];
        float gf = Gs[m * 68 + 16 + hl] + XGb[m * 64 + 16 + hl];
        float gg = Gs[m * 68 + 32 + hl] + XGb[m * 64 + 32 + hl];
        float go = Gs[m * 68 + 48 + hl] + XGb[m * 64 + 48 + hl];

        size_t sidx = (size_t)dir * NSPANS * H + (size_t)(m0 + m) * H + hhi;
        float cn = sigm(gf) * cbuf[m * 16 + hl] + sigm(gi) * tanhf(gg);
        float hn = sigm(go) * tanhf(cn);
        d_c[sidx]   = cn;
        h_out[sidx] = hn;
        if (t < lens[m]) d_sum[sidx] = sbuf[m * 16 + hl] + hn;
    }
}

// ---------------------------------------------------------------------------
// t=0 cell: gates = xg[offset[n]] (h=0). Writes h parity 0, c, sum.
// ---------------------------------------------------------------------------
__global__ void lstm_cell0(const int* __restrict__ slen)
{
    int idx = blockIdx.x * blockDim.x + threadIdx.x;
    if (idx >= 2 * NSPANS * H) return;
    int hh  = idx % H;
    int n   = (idx / H) % NSPANS;
    int dir = idx / (H * NSPANS);

    int row = d_offset[n];
    const float* g = d_xg + (size_t)dir * MROWS * G4 + (size_t)row * G4;
    float gi = g[hh];
    float gg = g[2 * H + hh];
    float go = g[3 * H + hh];

    float cn = sigm(gi) * tanhf(gg);
    float hn = sigm(go) * tanhf(cn);
    d_c[idx] = cn;
    d_h[idx] = hn;                  // parity 0
    d_sum[idx] = hn;                // slen >= 1
}

// ---------------------------------------------------------------------------
// Logits with smem-staged E. 512 threads, 32 spans x 16 ents. grid = 40.
// ---------------------------------------------------------------------------
__global__ __launch_bounds__(512)
void logits_kernel(const float* __restrict__ E, float* __restrict__ out)
{
    __shared__ float Es[NENT * 2 * H];
    int tid = threadIdx.x;
    for (int i = tid; i < NENT * 2 * H; i += 512)
        Es[i] = E[i];
    __syncthreads();

    int s = tid >> 4;
    int e = tid & 15;
    int n = blockIdx.x * 32 + s;

    const float4* sf = (const float4*)(d_sum + (size_t)n * H);
    const float4* sb = (const float4*)(d_sum + (size_t)NSPANS * H + (size_t)n * H);
    const float4* er = (const float4*)(Es + e * 2 * H);

    float acc = 0.f;
#pragma unroll
    for (int j = 0; j < H / 4; j++) {
        float4 a = sf[j], b = er[j];
        acc += a.x * b.x + a.y * b.y + a.z * b.z + a.w * b.w;
    }
#pragma unroll
    for (int j = 0; j < H / 4; j++) {
        float4 a = sb[j], b = er[H / 4 + j];
        acc += a.x * b.x + a.y * b.y + a.z * b.z + a.w * b.w;
    }
    out[n * NENT + e] = acc;
}

// ---------------------------------------------------------------------------
// Launch
// ---------------------------------------------------------------------------
extern "C" void kernel_launch(void* const* d_in, const int* in_sizes, int n_in,
                              void* d_out, int out_size)
{
    const float* hidden = (const float*)d_in[0];
    const int*   tok    = (const int*)d_in[1];
    const int*   slen   = (const int*)d_in[2];
    const int*   sbatch = (const int*)d_in[3];
    const float* W_ih_f = (const float*)d_in[4];
    const float* W_hh_f = (const float*)d_in[5];
    const float* b_ih_f = (const float*)d_in[6];
    const float* b_hh_f = (const float*)d_in[7];
    const float* W_ih_b = (const float*)d_in[8];
    const float* W_hh_b = (const float*)d_in[9];
    const float* b_ih_b = (const float*)d_in[10];
    const float* b_hh_b = (const float*)d_in[11];
    const float* E      = (const float*)d_in[12];
    float* out          = (float*)d_out;

    // 0. Compaction
    compact_kernel<<<1, 256>>>(slen);

    // 1. xg GEMM, fused gather, compacted rows: grid 13 x 50 x 2 (self-trim)
    {
        dim3 grid((G4 + 63) / 64, MROWS / 128, 2);
        gemm_xg_kernel<<<grid, 256>>>(hidden, tok, slen, sbatch,
                                      W_ih_f, b_ih_f, b_hh_f,
                                      W_ih_b, b_ih_b, b_hh_b);
    }

    // 2. Recurrence
    {
        const int ct = 256;
        lstm_cell0<<<(2 * NSPANS * H + ct - 1) / ct, ct>>>(slen);
    }
    for (int t = 1; t < LMAX; t++) {
        dim3 grid((H + 15) / 16, NSPANS / 64, 2);   // 13 x 20 x 2
        gemm_hh_cell_kernel<<<grid, 256>>>(W_hh_f, W_hh_b, slen, t);
    }

    // 3. Logits
    logits_kernel<<<NSPANS / 32, 512>>>(E, out);
}